// round 15
// baseline (speedup 1.0000x reference)
#include <cuda_runtime.h>
#include <cuda_bf16.h>
#include <math.h>
#include <stdint.h>

#define BB 8
#define CC 512
#define HH 32
#define WW 32
#define LL 1024   // H*W
#define NHD 8
#define HD 64
#define WHALF 16  // WINDOW/2

// ---------------- scratch (static device globals; no runtime allocation) ----
__device__ float g_xwalze[BB*CC*HH*WW];          // (B,C,H,W) post-walze
__device__ __nv_bfloat16 g_comb[BB*LL*2*CC];     // (B*L, 2C): [before | after]
__device__ float g_mask[BB*LL];                  // soft mask
__device__ __nv_bfloat16 g_qkv[BB*LL*3*CC];      // (B*L, 3C) bf16, Q pre-scaled
__device__ __nv_bfloat16 g_ctx[BB*LL*CC];        // attention context (bf16)
__device__ __nv_bfloat16 g_ipw[3*CC*CC];         // bf16 in_proj_w
__device__ __nv_bfloat16 g_opw[CC*CC];           // bf16 out_proj_w
__device__ __nv_bfloat16 g_w1[128*2*CC];         // bf16 det_w1

__device__ __forceinline__ float gelu_exact(float v) {
    return 0.5f * v * (1.0f + erff(v * 0.70710678118654752440f));
}
__device__ __forceinline__ uint32_t smem_u32(const void* p) {
    uint32_t a;
    asm("{ .reg .u64 t; cvta.to.shared.u64 t, %1; cvt.u32.u64 %0, t; }"
        : "=r"(a) : "l"(p));
    return a;
}
__device__ __forceinline__ void cp16(uint32_t dst, const void* src) {
    asm volatile("cp.async.cg.shared.global [%0], [%1], 16;" :: "r"(dst), "l"(src));
}
__device__ __forceinline__ void ldmx4(uint32_t addr, uint32_t& r0, uint32_t& r1,
                                      uint32_t& r2, uint32_t& r3) {
    asm volatile("ldmatrix.sync.aligned.m8n8.x4.shared.b16 {%0,%1,%2,%3}, [%4];"
                 : "=r"(r0), "=r"(r1), "=r"(r2), "=r"(r3) : "r"(addr));
}
__device__ __forceinline__ void ldmx2(uint32_t addr, uint32_t& r0, uint32_t& r1) {
    asm volatile("ldmatrix.sync.aligned.m8n8.x2.shared.b16 {%0,%1}, [%2];"
                 : "=r"(r0), "=r"(r1) : "r"(addr));
}
__device__ __forceinline__ void mma16(float* c, uint32_t a0, uint32_t a1,
                                      uint32_t a2, uint32_t a3,
                                      uint32_t b0, uint32_t b1) {
    asm volatile("mma.sync.aligned.m16n8k16.row.col.f32.bf16.bf16.f32 "
                 "{%0,%1,%2,%3}, {%4,%5,%6,%7}, {%8,%9}, {%0,%1,%2,%3};"
                 : "+f"(c[0]), "+f"(c[1]), "+f"(c[2]), "+f"(c[3])
                 : "r"(a0), "r"(a1), "r"(a2), "r"(a3), "r"(b0), "r"(b1));
}
__device__ __forceinline__ uint32_t bf2pack(float a, float b) {
    __nv_bfloat162 t = __floats2bfloat162_rn(a, b);
    return *(uint32_t*)&t;
}
__device__ __forceinline__ void stcs4(float* p, float4 v) {
    asm volatile("st.global.cs.v4.f32 [%0], {%1,%2,%3,%4};"
                 :: "l"(p), "f"(v.x), "f"(v.y), "f"(v.z), "f"(v.w) : "memory");
}

// ====== bf16 mma.sync GEMM body (validated) =================================
// EPI: 1 = bf16 store with Q-column 0.125 scaling, 2 = detector head,
//      3 = fused gated combine (smem-staged coalesced, MLP-batched).
template<int EPI, int MT>
__device__ __forceinline__ void
gemm_body(int bm, int bn,
          const __nv_bfloat16* __restrict__ A, int lda,
          const __nv_bfloat16* __restrict__ Bm, int ldb,
          const float* __restrict__ bias,
          float* __restrict__ Cm, int ldc, int K,
          const float* __restrict__ aux1,   // EPI2: w2    EPI3: mask
          const float* __restrict__ aux2,   // EPI2: b2    EPI3: xwalze
          char* smem)
{
    constexpr int TM = MT * 32;
    constexpr int ABYTES = TM * 128;
    constexpr int BUFB = ABYTES + 16384;
    const uint32_t sb = smem_u32(smem);
    const int tid = threadIdx.x, lane = tid & 31, wid = tid >> 5;
    const int wm0 = (wid & 1) * (TM / 2), wn0 = (wid >> 1) * 32;

    const int ld_row = tid >> 3;
    const uint32_t st_off =
        (uint32_t)(ld_row * 128 + (((tid & 7) * 16) ^ ((ld_row & 7) << 4)));
    const __nv_bfloat16* Agb = A  + (size_t)(bm + ld_row) * lda + (tid & 7) * 8;
    const __nv_bfloat16* Bgb = Bm + (size_t)(bn + ld_row) * ldb + (tid & 7) * 8;

    auto load_tile = [&](int buf, int ch) {
        uint32_t da = sb + buf * BUFB + st_off;
        uint32_t db = da + ABYTES;
        const __nv_bfloat16* sa  = Agb + ch * 64;
        const __nv_bfloat16* sbp = Bgb + ch * 64;
#pragma unroll
        for (int p = 0; p < MT; p++)
            cp16(da + p * 4096, sa + (size_t)p * 32 * lda);
#pragma unroll
        for (int p = 0; p < 4; p++)
            cp16(db + p * 4096, sbp + (size_t)p * 32 * ldb);
        asm volatile("cp.async.commit_group;" ::: "memory");
    };

    const int arow  = wm0 + (lane & 15);
    const uint32_t akb = ((uint32_t)(lane >> 4)) << 4;
    const uint32_t aswz = (uint32_t)((arow & 7) << 4);
    const uint32_t a_rowbase = (uint32_t)(arow * 128);
    const int brow  = wn0 + ((lane >> 4) << 3) + (lane & 7);
    const uint32_t bkb = (uint32_t)(((lane >> 3) & 1) << 4);
    const uint32_t bswz = (uint32_t)((brow & 7) << 4);
    const uint32_t b_rowbase = (uint32_t)(ABYTES + brow * 128);

    float c[MT][4][4];
#pragma unroll
    for (int i = 0; i < MT; i++)
#pragma unroll
        for (int j = 0; j < 4; j++)
#pragma unroll
            for (int k = 0; k < 4; k++) c[i][j][k] = 0.0f;

    const int nch = K >> 6;
    load_tile(0, 0);
    load_tile(1, 1);

    for (int ch = 0; ch < nch; ch++) {
        const int buf = ch % 3;
        if (ch + 1 < nch) asm volatile("cp.async.wait_group 1;" ::: "memory");
        else              asm volatile("cp.async.wait_group 0;" ::: "memory");
        __syncthreads();
        if (ch + 2 < nch) load_tile((ch + 2) % 3, ch + 2);

        const uint32_t base = sb + buf * BUFB;
#pragma unroll
        for (int ks = 0; ks < 4; ks++) {
            const uint32_t kso = (uint32_t)(ks * 32);
            uint32_t a[MT][4];
#pragma unroll
            for (int mt = 0; mt < MT; mt++)
                ldmx4(base + a_rowbase + (uint32_t)(mt * 2048) + ((kso + akb) ^ aswz),
                      a[mt][0], a[mt][1], a[mt][2], a[mt][3]);
            uint32_t b[4][2];
#pragma unroll
            for (int nt2 = 0; nt2 < 2; nt2++)
                ldmx4(base + b_rowbase + (uint32_t)(nt2 * 2048) + ((kso + bkb) ^ bswz),
                      b[nt2*2][0], b[nt2*2][1], b[nt2*2+1][0], b[nt2*2+1][1]);
#pragma unroll
            for (int mt = 0; mt < MT; mt++)
#pragma unroll
                for (int nt = 0; nt < 4; nt++)
                    mma16(c[mt][nt], a[mt][0], a[mt][1], a[mt][2], a[mt][3],
                          b[nt][0], b[nt][1]);
        }
    }

    if (EPI == 1) {
        __nv_bfloat16* Cb = (__nv_bfloat16*)Cm;
#pragma unroll
        for (int mt = 0; mt < MT; mt++) {
            const int r0 = bm + wm0 + mt * 16 + (lane >> 2);
#pragma unroll
            for (int nt = 0; nt < 4; nt++) {
                const int col = bn + wn0 + nt * 8 + (lane & 3) * 2;
                float2 bs = *(const float2*)(bias + col);
                float sc = (col < 512) ? 0.125f : 1.0f;
                float v0 = (c[mt][nt][0] + bs.x) * sc;
                float v1 = (c[mt][nt][1] + bs.y) * sc;
                float v2 = (c[mt][nt][2] + bs.x) * sc;
                float v3 = (c[mt][nt][3] + bs.y) * sc;
                *(uint32_t*)(Cb + (size_t)r0 * ldc + col)       = bf2pack(v0, v1);
                *(uint32_t*)(Cb + (size_t)(r0 + 8) * ldc + col) = bf2pack(v2, v3);
            }
        }
        return;
    }

    if (EPI == 2) {
        float* red = (float*)smem;
        __syncthreads();
        if (tid < TM) red[tid] = 0.0f;
        __syncthreads();
#pragma unroll
        for (int mt = 0; mt < MT; mt++) {
            float pA = 0.0f, pB = 0.0f;
#pragma unroll
            for (int nt = 0; nt < 4; nt++) {
                int col = bn + wn0 + nt * 8 + (lane & 3) * 2;
                float2 bs = *(const float2*)(bias + col);
                float w0 = aux1[col], w1 = aux1[col + 1];
                pA += gelu_exact(c[mt][nt][0] + bs.x) * w0
                    + gelu_exact(c[mt][nt][1] + bs.y) * w1;
                pB += gelu_exact(c[mt][nt][2] + bs.x) * w0
                    + gelu_exact(c[mt][nt][3] + bs.y) * w1;
            }
            pA += __shfl_xor_sync(0xffffffffu, pA, 1);
            pA += __shfl_xor_sync(0xffffffffu, pA, 2);
            pB += __shfl_xor_sync(0xffffffffu, pB, 1);
            pB += __shfl_xor_sync(0xffffffffu, pB, 2);
            if ((lane & 3) == 0) {
                int rA = wm0 + mt * 16 + (lane >> 2);
                atomicAdd(&red[rA], pA);
                atomicAdd(&red[rA + 8], pB);
            }
        }
        __syncthreads();
        if (tid < TM)
            Cm[bm + tid] = 1.0f / (1.0f + __expf(-(red[tid] + aux2[0])));
        return;
    }

    if (EPI == 3) {
        constexpr int SROW = TM + 8;
        float* stage = (float*)smem;
        __syncthreads();
#pragma unroll
        for (int mt = 0; mt < MT; mt++) {
            const int row = wm0 + mt * 16 + (lane >> 2);
#pragma unroll
            for (int nt = 0; nt < 4; nt++) {
                const int col = wn0 + nt * 8 + (lane & 3) * 2;
                float2 bs = *(const float2*)(bias + bn + col);
                stage[col*SROW + row]           = c[mt][nt][0] + bs.x;
                stage[(col+1)*SROW + row]       = c[mt][nt][1] + bs.y;
                stage[col*SROW + row + 8]       = c[mt][nt][2] + bs.x;
                stage[(col+1)*SROW + row + 8]   = c[mt][nt][3] + bs.y;
            }
        }
        __syncthreads();
        const int bloc = bm >> 10, l0 = bm & (LL - 1);
        if (MT == 4) {
            // 128 l per CTA: full warp of float4 per c-row
            float4 mk = *(const float4*)(aux1 + bm + lane * 4);
#pragma unroll
            for (int g = 0; g < 4; g++) {
                size_t oo[4];
                float4 xw[4];
#pragma unroll
                for (int j = 0; j < 4; j++) {
                    int cr = wid + (g * 4 + j) * 8;
                    oo[j] = ((size_t)(bloc*CC + bn + cr)) * LL + l0 + lane*4;
                    xw[j] = *(const float4*)(aux2 + oo[j]);
                }
#pragma unroll
                for (int j = 0; j < 4; j++) {
                    int cr = wid + (g * 4 + j) * 8;
                    float4 vv = *(const float4*)&stage[cr*SROW + lane*4];
                    float4 r;
                    r.x = xw[j].x + mk.x * vv.x;
                    r.y = xw[j].y + mk.y * vv.y;
                    r.z = xw[j].z + mk.z * vv.z;
                    r.w = xw[j].w + mk.w * vv.w;
                    stcs4(Cm + oo[j], r);
                }
            }
        } else {
            // TM == 64: 64 l per CTA, 2 c-rows per warp, 16 lanes x float4
            const int lhalf = lane >> 4;
            const int l4 = (lane & 15) * 4;
            float4 mk = *(const float4*)(aux1 + bm + l4);
#pragma unroll
            for (int g = 0; g < 2; g++) {
                size_t oo[4];
                float4 xw[4];
#pragma unroll
                for (int j = 0; j < 4; j++) {
                    int cr = (g * 4 + j) * 16 + wid * 2 + lhalf;
                    oo[j] = ((size_t)(bloc*CC + bn + cr)) * LL + l0 + l4;
                    xw[j] = *(const float4*)(aux2 + oo[j]);
                }
#pragma unroll
                for (int j = 0; j < 4; j++) {
                    int cr = (g * 4 + j) * 16 + wid * 2 + lhalf;
                    float4 vv = *(const float4*)&stage[cr*SROW + l4];
                    float4 r;
                    r.x = xw[j].x + mk.x * vv.x;
                    r.y = xw[j].y + mk.y * vv.y;
                    r.z = xw[j].z + mk.z * vv.z;
                    r.w = xw[j].w + mk.w * vv.w;
                    stcs4(Cm + oo[j], r);
                }
            }
        }
        return;
    }
}

// ---- fused launch: QKV GEMM (768 CTAs, MT=4) + detector (128 CTAs) ---------
#define QKV_BLOCKS 768
#define FUSED_SMEM (3 * (128*128 + 16384))   // 98304
__global__ void __launch_bounds__(256, 2)
fused_qkv_det(const __nv_bfloat16* __restrict__ comb,
              const __nv_bfloat16* __restrict__ ipw,
              const float* __restrict__ ipb,
              __nv_bfloat16* __restrict__ qkv,
              const __nv_bfloat16* __restrict__ w1,
              const float* __restrict__ det_b1,
              const float* __restrict__ det_w2,
              const float* __restrict__ det_b2,
              float* __restrict__ mask)
{
    extern __shared__ char smem[];
    int bx = blockIdx.x;
    if (bx < QKV_BLOCKS) {
        int bn = (bx % 12) * 128;
        int bm = (bx / 12) * 128;
        gemm_body<1,4>(bm, bn, comb + CC, 2*CC, ipw, CC, ipb,
                       (float*)qkv, 3*CC, CC, nullptr, nullptr, smem);
    } else {
        int bm = (bx - QKV_BLOCKS) * 64;
        gemm_body<2,2>(bm, 0, comb, 2*CC, w1, 2*CC, det_b1,
                       mask, 1, 2*CC, det_w2, det_b2, smem);
    }
}

// ---- out_proj GEMM fused with gated combine: MT=2, 3 CTAs/SM ---------------
#define OUTPROJ_SMEM (3 * (64*128 + 16384))   // 73728
__global__ void __launch_bounds__(256, 3)
outproj_combine(const __nv_bfloat16* __restrict__ ctx,
                const __nv_bfloat16* __restrict__ opw,
                const float* __restrict__ opb,
                float* __restrict__ out,
                const float* __restrict__ mask,
                const float* __restrict__ xwalze)
{
    extern __shared__ char smem[];
    gemm_body<3,2>(blockIdx.y * 64, blockIdx.x * 128, ctx, CC, opw, CC,
                   opb, out, 0, CC, mask, xwalze, smem);
}

// ==== fused walze: full-plane conv/BN/GELU + comb pack + xwalze, 1 launch ====
#define WCH 8
#define WPAD 1028
#define WALZE_PLANES 512                            // 8 b x 64 ct
#define RW_TOTAL (3*CC*CC + CC*CC + 128*2*CC)       // 1,179,648
#define RW_BLOCKS ((RW_TOTAL + 255)/256)            // 4608
#define WALZE_SMEM ((WCH*WPAD + WCH*136) * 4)       // 37248 B

__global__ void __launch_bounds__(256)
walze_fused(const float* __restrict__ x,
            const float* __restrict__ dw_w,
            const float* __restrict__ dw_b,
            const float* __restrict__ sh_w,
            const float* __restrict__ sh_b,
            const float* __restrict__ mixw,
            const float* __restrict__ gamma,
            const float* __restrict__ beta,
            const float* __restrict__ ipw,
            const float* __restrict__ opw,
            const float* __restrict__ w1)
{
    int bi = blockIdx.x;
    int tid = threadIdx.x;
    if (bi >= WALZE_PLANES) {
        int i = (bi - WALZE_PLANES) * 256 + tid;
        const int N1 = 3*CC*CC, N2 = CC*CC, N3 = 128*2*CC;
        if (i < N1)                 g_ipw[i] = __float2bfloat16_rn(ipw[i]);
        else if (i < N1 + N2)       g_opw[i - N1] = __float2bfloat16_rn(opw[i - N1]);
        else if (i < N1 + N2 + N3)  g_w1[i - N1 - N2] = __float2bfloat16_rn(w1[i - N1 - N2]);
        return;
    }
    extern __shared__ float sx[];            // [WCH][WPAD]
    float* swo = sx + WCH * WPAD;            // [WCH][136]

    int ct = bi & 63, b = bi >> 6;
    int c0 = ct * WCH;

    for (int i = tid; i < WCH * 256; i += 256) {
        int c = i >> 8, l4 = (i & 255) * 4;
        float4 v = *(const float4*)(x + ((size_t)(b*CC + c0 + c)) * LL + l4);
        *(float4*)(sx + c * WPAD + l4) = v;
    }
    __syncthreads();

    const int c = tid & 7;
    const int lb = tid >> 3;                 // 0..31
    const float* dk = dw_w + (c0 + c) * 9;
    float d0 = dk[0], d1 = dk[1], d2 = dk[2], d3 = dk[3], d4 = dk[4],
          d5 = dk[5], d6 = dk[6], d7 = dk[7], d8 = dk[8];
    float dwb = dw_b[c0 + c];
    float gm = gamma[c0 + c] * rsqrtf(1.0f + 1e-5f);
    float bt = beta[c0 + c];
    float s0 = sh_w[0], s1 = sh_w[1], s2 = sh_w[2], s3 = sh_w[3], s4 = sh_w[4],
          s5 = sh_w[5], s6 = sh_w[6], s7 = sh_w[7], s8 = sh_w[8];
    float shb = sh_b[0];
    float mix = 1.0f / (1.0f + __expf(-mixw[0]));
    const float* row = sx + c * WPAD;

    for (int k = 0; k < 8; k++) {
#pragma unroll
        for (int j = 0; j < 4; j++) {
            int ll = lb + 32 * j;            // 0..127 within slab
            int l = k * 128 + ll;
            int h = l >> 5, w = l & 31;
            int hm = (h + 31) & 31, hp = (h + 1) & 31;
            int wm = (w + 31) & 31, wp = (w + 1) & 31;
            float v00 = row[hm*32+wm], v01 = row[hm*32+w], v02 = row[hm*32+wp];
            float v10 = row[h*32+wm],  v11 = row[h*32+w],  v12 = row[h*32+wp];
            float v20 = row[hp*32+wm], v21 = row[hp*32+w], v22 = row[hp*32+wp];
            float mo = v00*d0 + v01*d1 + v02*d2 + v10*d3 + v11*d4 + v12*d5
                     + v20*d6 + v21*d7 + v22*d8 + dwb;
            float ex = v00*s0 + v01*s1 + v02*s2 + v10*s3 + v11*s4 + v12*s5
                     + v20*s6 + v21*s7 + v22*s8 + shb;
            float xw = gelu_exact(gm * (mix*mo + (1.0f-mix)*ex + v11) + bt);
            size_t dst = ((size_t)(b*LL + l)) * (2*CC) + c0 + c;
            g_comb[dst]      = __float2bfloat16_rn(v11);
            g_comb[dst + CC] = __float2bfloat16_rn(xw);
            swo[c * 136 + ll] = xw;
        }
        __syncthreads();
#pragma unroll
        for (int j = 0; j < 4; j++) {
            int idx = tid + 256 * j;         // 0..1023
            int c2 = idx >> 7, l2 = idx & 127;
            g_xwalze[((size_t)(b*CC + c0 + c2)) * LL + k*128 + l2] =
                swo[c2 * 136 + l2];
        }
        __syncthreads();
    }
}

// ============ banded attention via mma: S = QK^T, ctx = P V =================
#define ATT_VT  0                        // 64 x 208
#define ATT_LS  (ATT_VT + 64*208)        // 13312, 64 floats
#define ATT_Q   (ATT_LS + 256)           // 13568, 64 x 144
#define ATT_K   (ATT_Q + 64*144)         // 22784, 96 x 144
#define ATT_P   ATT_Q                    // aliases Q/K (needs 64*208 <= 23040)
#define ATT_SMEM (ATT_K + 96*144)        // 36608

__global__ void __launch_bounds__(256)
attn_kernel()
{
    extern __shared__ char smem[];
    const uint32_t sb = smem_u32(smem);
    int bi = blockIdx.x;
    int qt = bi & 15, h = (bi >> 4) & 7, b = bi >> 7;
    int q0 = qt * 64;
    int jlo = max(0, q0 - WHALF);
    int jhi = min(LL - 1, q0 + 63 + WHALF);
    int nrows = jhi - jlo + 1;              // 80 or 96
    int tid = threadIdx.x, lane = tid & 31, wid = tid >> 5;

    const __nv_bfloat16* qb = g_qkv + (size_t)(b*LL + q0) * (3*CC) + h*HD;
    for (int i = tid; i < 64*8; i += 256) {
        int r = i >> 3, cb = (i & 7) * 16;
        uint4 v = *(const uint4*)((const char*)(qb + (size_t)r * (3*CC)) + cb);
        *(uint4*)(smem + ATT_Q + r*144 + cb) = v;
    }
    const __nv_bfloat16* kb = g_qkv + (size_t)(b*LL + jlo) * (3*CC) + CC + h*HD;
    for (int i = tid; i < 96*8; i += 256) {
        int r = i >> 3, cb = (i & 7) * 16;
        uint4 v = make_uint4(0u, 0u, 0u, 0u);
        if (r < nrows)
            v = *(const uint4*)((const char*)(kb + (size_t)r * (3*CC)) + cb);
        *(uint4*)(smem + ATT_K + r*144 + cb) = v;
    }
    const __nv_bfloat16* vb = kb + CC;
    for (int i = tid; i < 96*16; i += 256) {
        int r = i >> 4, c4 = (i & 15) * 4;
        uint2 v = make_uint2(0u, 0u);
        if (r < nrows)
            v = *(const uint2*)(vb + (size_t)r * (3*CC) + c4);
        const __nv_bfloat16* hv = (const __nv_bfloat16*)&v;
        *(__nv_bfloat16*)(smem + ATT_VT + (c4+0)*208 + r*2) = hv[0];
        *(__nv_bfloat16*)(smem + ATT_VT + (c4+1)*208 + r*2) = hv[1];
        *(__nv_bfloat16*)(smem + ATT_VT + (c4+2)*208 + r*2) = hv[2];
        *(__nv_bfloat16*)(smem + ATT_VT + (c4+3)*208 + r*2) = hv[3];
    }
    if (tid < 64) ((float*)(smem + ATT_LS))[tid] = 0.0f;
    __syncthreads();

    const int wm0 = (wid & 1) * 32;
    const int wn0s = (wid >> 1) * 24;
    float s[2][3][4];
#pragma unroll
    for (int i = 0; i < 2; i++)
#pragma unroll
        for (int j = 0; j < 3; j++)
#pragma unroll
            for (int k = 0; k < 4; k++) s[i][j][k] = 0.0f;
    {
        const uint32_t aAddr = sb + ATT_Q + (uint32_t)((wm0 + (lane & 15)) * 144)
                             + ((uint32_t)(lane >> 4) << 4);
        const uint32_t bAddr4 = sb + ATT_K
                             + (uint32_t)((wn0s + ((lane >> 4) << 3) + (lane & 7)) * 144)
                             + (uint32_t)(((lane >> 3) & 1) << 4);
        const uint32_t bAddr2 = sb + ATT_K
                             + (uint32_t)((wn0s + 16 + (lane & 7)) * 144)
                             + (uint32_t)(((lane >> 3) & 1) << 4);
#pragma unroll
        for (int ks = 0; ks < 4; ks++) {
            const uint32_t kso = (uint32_t)(ks * 32);
            uint32_t a0[4], a1[4], bb[3][2];
            ldmx4(aAddr + kso,            a0[0], a0[1], a0[2], a0[3]);
            ldmx4(aAddr + 16*144 + kso,   a1[0], a1[1], a1[2], a1[3]);
            ldmx4(bAddr4 + kso, bb[0][0], bb[0][1], bb[1][0], bb[1][1]);
            ldmx2(bAddr2 + kso, bb[2][0], bb[2][1]);
#pragma unroll
            for (int nt = 0; nt < 3; nt++) {
                mma16(s[0][nt], a0[0], a0[1], a0[2], a0[3], bb[nt][0], bb[nt][1]);
                mma16(s[1][nt], a1[0], a1[1], a1[2], a1[3], bb[nt][0], bb[nt][1]);
            }
        }
    }
    __syncthreads();   // Q/K reads complete before P overwrites that region

    float* lsum = (float*)(smem + ATT_LS);
#pragma unroll
    for (int mt = 0; mt < 2; mt++) {
        int row = wm0 + mt * 16 + (lane >> 2);
        int qA = q0 + row, qB = qA + 8;
        float rs0 = 0.0f, rs1 = 0.0f;
#pragma unroll
        for (int nt = 0; nt < 3; nt++) {
            int col = wn0s + nt * 8 + (lane & 3) * 2;
            int gj0 = jlo + col, gj1 = gj0 + 1;
            bool a00 = (gj0 >= qA - WHALF) && (gj0 <= qA + WHALF) && (gj0 < LL);
            bool a01 = (gj1 >= qA - WHALF) && (gj1 <= qA + WHALF) && (gj1 < LL);
            bool a10 = (gj0 >= qB - WHALF) && (gj0 <= qB + WHALF) && (gj0 < LL);
            bool a11 = (gj1 >= qB - WHALF) && (gj1 <= qB + WHALF) && (gj1 < LL);
            float p00 = a00 ? __expf(s[mt][nt][0]) : 0.0f;
            float p01 = a01 ? __expf(s[mt][nt][1]) : 0.0f;
            float p10 = a10 ? __expf(s[mt][nt][2]) : 0.0f;
            float p11 = a11 ? __expf(s[mt][nt][3]) : 0.0f;
            rs0 += p00 + p01; rs1 += p10 + p11;
            *(uint32_t*)(smem + ATT_P + row*208 + col*2)     = bf2pack(p00, p01);
            *(uint32_t*)(smem + ATT_P + (row+8)*208 + col*2) = bf2pack(p10, p11);
        }
        rs0 += __shfl_xor_sync(0xffffffffu, rs0, 1);
        rs0 += __shfl_xor_sync(0xffffffffu, rs0, 2);
        rs1 += __shfl_xor_sync(0xffffffffu, rs1, 1);
        rs1 += __shfl_xor_sync(0xffffffffu, rs1, 2);
        if ((lane & 3) == 0) {
            atomicAdd(&lsum[row], rs0);
            atomicAdd(&lsum[row + 8], rs1);
        }
    }
    __syncthreads();

    const int wn0v = (wid >> 1) * 16;
    float o[2][2][4];
#pragma unroll
    for (int i = 0; i < 2; i++)
#pragma unroll
        for (int j = 0; j < 2; j++)
#pragma unroll
            for (int k = 0; k < 4; k++) o[i][j][k] = 0.0f;
    {
        const uint32_t aAddr = sb + ATT_P + (uint32_t)((wm0 + (lane & 15)) * 208)
                             + ((uint32_t)(lane >> 4) << 4);
        const uint32_t bAddr = sb + ATT_VT
                             + (uint32_t)((wn0v + ((lane >> 4) << 3) + (lane & 7)) * 208)
                             + (uint32_t)(((lane >> 3) & 1) << 4);
#pragma unroll
        for (int ks = 0; ks < 6; ks++) {
            const uint32_t kso = (uint32_t)(ks * 32);
            uint32_t a0[4], a1[4], bb[2][2];
            ldmx4(aAddr + kso,          a0[0], a0[1], a0[2], a0[3]);
            ldmx4(aAddr + 16*208 + kso, a1[0], a1[1], a1[2], a1[3]);
            ldmx4(bAddr + kso, bb[0][0], bb[0][1], bb[1][0], bb[1][1]);
#pragma unroll
            for (int nt = 0; nt < 2; nt++) {
                mma16(o[0][nt], a0[0], a0[1], a0[2], a0[3], bb[nt][0], bb[nt][1]);
                mma16(o[1][nt], a1[0], a1[1], a1[2], a1[3], bb[nt][0], bb[nt][1]);
            }
        }
    }

#pragma unroll
    for (int mt = 0; mt < 2; mt++) {
        int row = wm0 + mt * 16 + (lane >> 2);
        float inv0 = 1.0f / lsum[row];
        float inv1 = 1.0f / lsum[row + 8];
#pragma unroll
        for (int nt = 0; nt < 2; nt++) {
            int col = wn0v + nt * 8 + (lane & 3) * 2;
            __nv_bfloat16* d0 = g_ctx + (size_t)(b*LL + q0 + row) * CC + h*HD + col;
            __nv_bfloat16* d1 = d0 + (size_t)8 * CC;
            *(uint32_t*)d0 = bf2pack(o[mt][nt][0] * inv0, o[mt][nt][1] * inv0);
            *(uint32_t*)d1 = bf2pack(o[mt][nt][2] * inv1, o[mt][nt][3] * inv1);
        }
    }
}

// ---------------- host launcher ---------------------------------------------
extern "C" void kernel_launch(void* const* d_in, const int* in_sizes, int n_in,
                              void* d_out, int out_size)
{
    const float* x      = (const float*)d_in[0];
    const float* dw_w   = (const float*)d_in[1];
    const float* dw_b   = (const float*)d_in[2];
    const float* sh_w   = (const float*)d_in[3];
    const float* sh_b   = (const float*)d_in[4];
    const float* mixw   = (const float*)d_in[5];
    const float* gamma  = (const float*)d_in[6];
    const float* beta   = (const float*)d_in[7];
    const float* det_w1 = (const float*)d_in[8];
    const float* det_b1 = (const float*)d_in[9];
    const float* det_w2 = (const float*)d_in[10];
    const float* det_b2 = (const float*)d_in[11];
    const float* ipw    = (const float*)d_in[12];
    const float* ipb    = (const float*)d_in[13];
    const float* opw    = (const float*)d_in[14];
    const float* opb    = (const float*)d_in[15];
    float* out = (float*)d_out;

    __nv_bfloat16 *p_comb, *p_ctx, *p_ipw, *p_opw, *p_w1, *p_qkv;
    float *p_mask, *p_xwalze;
    cudaGetSymbolAddress((void**)&p_comb,    g_comb);
    cudaGetSymbolAddress((void**)&p_qkv,     g_qkv);
    cudaGetSymbolAddress((void**)&p_ctx,     g_ctx);
    cudaGetSymbolAddress((void**)&p_ipw,     g_ipw);
    cudaGetSymbolAddress((void**)&p_opw,     g_opw);
    cudaGetSymbolAddress((void**)&p_w1,      g_w1);
    cudaGetSymbolAddress((void**)&p_mask,    g_mask);
    cudaGetSymbolAddress((void**)&p_xwalze,  g_xwalze);

    cudaFuncSetAttribute((const void*)fused_qkv_det,
                         cudaFuncAttributeMaxDynamicSharedMemorySize, FUSED_SMEM);
    cudaFuncSetAttribute((const void*)outproj_combine,
                         cudaFuncAttributeMaxDynamicSharedMemorySize, OUTPROJ_SMEM);
    cudaFuncSetAttribute((const void*)attn_kernel,
                         cudaFuncAttributeMaxDynamicSharedMemorySize, ATT_SMEM);
    cudaFuncSetAttribute((const void*)walze_fused,
                         cudaFuncAttributeMaxDynamicSharedMemorySize, WALZE_SMEM);

    // 1) fused walze: conv/BN/GELU + comb pack + xwalze (+ weight rounding tail)
    walze_fused<<<WALZE_PLANES + RW_BLOCKS, 256, WALZE_SMEM>>>(
        x, dw_w, dw_b, sh_w, sh_b, mixw, gamma, beta, ipw, opw, det_w1);

    // 2) fused QKV GEMM (bf16 out, Q pre-scaled) + detector GEMM/head
    fused_qkv_det<<<QKV_BLOCKS + 128, 256, FUSED_SMEM>>>(
        p_comb, p_ipw, ipb, p_qkv, p_w1, det_b1, det_w2, det_b2, p_mask);

    // 3) banded attention (mma-based, bf16 I/O)
    attn_kernel<<<BB*NHD*(LL/64), 256, ATT_SMEM>>>();

    // 4) out_proj GEMM fused with gated combine: MT=2, 512 CTAs, 3/SM -> out
    {
        dim3 g(CC/128, (BB*LL)/64);
        outproj_combine<<<g, 256, OUTPROJ_SMEM>>>(p_ctx, p_opw, opb, out,
                                                  p_mask, p_xwalze);
    }
}

// round 16
// speedup vs baseline: 1.0225x; 1.0225x over previous
#include <cuda_runtime.h>
#include <cuda_bf16.h>
#include <math.h>
#include <stdint.h>

#define BB 8
#define CC 512
#define HH 32
#define WW 32
#define LL 1024   // H*W
#define NHD 8
#define HD 64
#define WHALF 16  // WINDOW/2

// ---------------- scratch (static device globals; no runtime allocation) ----
__device__ float g_xwalze[BB*CC*HH*WW];          // (B,C,H,W) post-walze
__device__ __nv_bfloat16 g_comb[BB*LL*2*CC];     // (B*L, 2C): [before | after]
__device__ float g_mask[BB*LL];                  // soft mask
__device__ __nv_bfloat16 g_qkv[BB*LL*3*CC];      // (B*L, 3C) bf16, Q pre-scaled
__device__ __nv_bfloat16 g_ctx[BB*LL*CC];        // attention context (bf16)
__device__ __nv_bfloat16 g_ipw[3*CC*CC];         // bf16 in_proj_w
__device__ __nv_bfloat16 g_opw[CC*CC];           // bf16 out_proj_w
__device__ __nv_bfloat16 g_w1[128*2*CC];         // bf16 det_w1

__device__ __forceinline__ float gelu_exact(float v) {
    return 0.5f * v * (1.0f + erff(v * 0.70710678118654752440f));
}
__device__ __forceinline__ uint32_t smem_u32(const void* p) {
    uint32_t a;
    asm("{ .reg .u64 t; cvta.to.shared.u64 t, %1; cvt.u32.u64 %0, t; }"
        : "=r"(a) : "l"(p));
    return a;
}
__device__ __forceinline__ void cp16(uint32_t dst, const void* src) {
    asm volatile("cp.async.cg.shared.global [%0], [%1], 16;" :: "r"(dst), "l"(src));
}
__device__ __forceinline__ void ldmx4(uint32_t addr, uint32_t& r0, uint32_t& r1,
                                      uint32_t& r2, uint32_t& r3) {
    asm volatile("ldmatrix.sync.aligned.m8n8.x4.shared.b16 {%0,%1,%2,%3}, [%4];"
                 : "=r"(r0), "=r"(r1), "=r"(r2), "=r"(r3) : "r"(addr));
}
__device__ __forceinline__ void ldmx2(uint32_t addr, uint32_t& r0, uint32_t& r1) {
    asm volatile("ldmatrix.sync.aligned.m8n8.x2.shared.b16 {%0,%1}, [%2];"
                 : "=r"(r0), "=r"(r1) : "r"(addr));
}
__device__ __forceinline__ void mma16(float* c, uint32_t a0, uint32_t a1,
                                      uint32_t a2, uint32_t a3,
                                      uint32_t b0, uint32_t b1) {
    asm volatile("mma.sync.aligned.m16n8k16.row.col.f32.bf16.bf16.f32 "
                 "{%0,%1,%2,%3}, {%4,%5,%6,%7}, {%8,%9}, {%0,%1,%2,%3};"
                 : "+f"(c[0]), "+f"(c[1]), "+f"(c[2]), "+f"(c[3])
                 : "r"(a0), "r"(a1), "r"(a2), "r"(a3), "r"(b0), "r"(b1));
}
__device__ __forceinline__ uint32_t bf2pack(float a, float b) {
    __nv_bfloat162 t = __floats2bfloat162_rn(a, b);
    return *(uint32_t*)&t;
}
__device__ __forceinline__ void stcs4(float* p, float4 v) {
    asm volatile("st.global.cs.v4.f32 [%0], {%1,%2,%3,%4};"
                 :: "l"(p), "f"(v.x), "f"(v.y), "f"(v.z), "f"(v.w) : "memory");
}

// ====== bf16 mma.sync GEMM body (validated) =================================
// EPI: 1 = bf16 store with Q-column 0.125 scaling, 2 = detector head,
//      3 = fused gated combine (smem-staged coalesced, MLP-batched).
template<int EPI, int MT>
__device__ __forceinline__ void
gemm_body(int bm, int bn,
          const __nv_bfloat16* __restrict__ A, int lda,
          const __nv_bfloat16* __restrict__ Bm, int ldb,
          const float* __restrict__ bias,
          float* __restrict__ Cm, int ldc, int K,
          const float* __restrict__ aux1,   // EPI2: w2    EPI3: mask
          const float* __restrict__ aux2,   // EPI2: b2    EPI3: xwalze
          char* smem)
{
    constexpr int TM = MT * 32;
    constexpr int ABYTES = TM * 128;
    constexpr int BUFB = ABYTES + 16384;
    const uint32_t sb = smem_u32(smem);
    const int tid = threadIdx.x, lane = tid & 31, wid = tid >> 5;
    const int wm0 = (wid & 1) * (TM / 2), wn0 = (wid >> 1) * 32;

    const int ld_row = tid >> 3;
    const uint32_t st_off =
        (uint32_t)(ld_row * 128 + (((tid & 7) * 16) ^ ((ld_row & 7) << 4)));
    const __nv_bfloat16* Agb = A  + (size_t)(bm + ld_row) * lda + (tid & 7) * 8;
    const __nv_bfloat16* Bgb = Bm + (size_t)(bn + ld_row) * ldb + (tid & 7) * 8;

    auto load_tile = [&](int buf, int ch) {
        uint32_t da = sb + buf * BUFB + st_off;
        uint32_t db = da + ABYTES;
        const __nv_bfloat16* sa  = Agb + ch * 64;
        const __nv_bfloat16* sbp = Bgb + ch * 64;
#pragma unroll
        for (int p = 0; p < MT; p++)
            cp16(da + p * 4096, sa + (size_t)p * 32 * lda);
#pragma unroll
        for (int p = 0; p < 4; p++)
            cp16(db + p * 4096, sbp + (size_t)p * 32 * ldb);
        asm volatile("cp.async.commit_group;" ::: "memory");
    };

    const int arow  = wm0 + (lane & 15);
    const uint32_t akb = ((uint32_t)(lane >> 4)) << 4;
    const uint32_t aswz = (uint32_t)((arow & 7) << 4);
    const uint32_t a_rowbase = (uint32_t)(arow * 128);
    const int brow  = wn0 + ((lane >> 4) << 3) + (lane & 7);
    const uint32_t bkb = (uint32_t)(((lane >> 3) & 1) << 4);
    const uint32_t bswz = (uint32_t)((brow & 7) << 4);
    const uint32_t b_rowbase = (uint32_t)(ABYTES + brow * 128);

    float c[MT][4][4];
#pragma unroll
    for (int i = 0; i < MT; i++)
#pragma unroll
        for (int j = 0; j < 4; j++)
#pragma unroll
            for (int k = 0; k < 4; k++) c[i][j][k] = 0.0f;

    const int nch = K >> 6;
    load_tile(0, 0);
    load_tile(1, 1);

    for (int ch = 0; ch < nch; ch++) {
        const int buf = ch % 3;
        if (ch + 1 < nch) asm volatile("cp.async.wait_group 1;" ::: "memory");
        else              asm volatile("cp.async.wait_group 0;" ::: "memory");
        __syncthreads();
        if (ch + 2 < nch) load_tile((ch + 2) % 3, ch + 2);

        const uint32_t base = sb + buf * BUFB;
#pragma unroll
        for (int ks = 0; ks < 4; ks++) {
            const uint32_t kso = (uint32_t)(ks * 32);
            uint32_t a[MT][4];
#pragma unroll
            for (int mt = 0; mt < MT; mt++)
                ldmx4(base + a_rowbase + (uint32_t)(mt * 2048) + ((kso + akb) ^ aswz),
                      a[mt][0], a[mt][1], a[mt][2], a[mt][3]);
            uint32_t b[4][2];
#pragma unroll
            for (int nt2 = 0; nt2 < 2; nt2++)
                ldmx4(base + b_rowbase + (uint32_t)(nt2 * 2048) + ((kso + bkb) ^ bswz),
                      b[nt2*2][0], b[nt2*2][1], b[nt2*2+1][0], b[nt2*2+1][1]);
#pragma unroll
            for (int mt = 0; mt < MT; mt++)
#pragma unroll
                for (int nt = 0; nt < 4; nt++)
                    mma16(c[mt][nt], a[mt][0], a[mt][1], a[mt][2], a[mt][3],
                          b[nt][0], b[nt][1]);
        }
    }

    if (EPI == 1) {
        __nv_bfloat16* Cb = (__nv_bfloat16*)Cm;
#pragma unroll
        for (int mt = 0; mt < MT; mt++) {
            const int r0 = bm + wm0 + mt * 16 + (lane >> 2);
#pragma unroll
            for (int nt = 0; nt < 4; nt++) {
                const int col = bn + wn0 + nt * 8 + (lane & 3) * 2;
                float2 bs = *(const float2*)(bias + col);
                float sc = (col < 512) ? 0.125f : 1.0f;
                float v0 = (c[mt][nt][0] + bs.x) * sc;
                float v1 = (c[mt][nt][1] + bs.y) * sc;
                float v2 = (c[mt][nt][2] + bs.x) * sc;
                float v3 = (c[mt][nt][3] + bs.y) * sc;
                *(uint32_t*)(Cb + (size_t)r0 * ldc + col)       = bf2pack(v0, v1);
                *(uint32_t*)(Cb + (size_t)(r0 + 8) * ldc + col) = bf2pack(v2, v3);
            }
        }
        return;
    }

    if (EPI == 2) {
        float* red = (float*)smem;
        __syncthreads();
        if (tid < TM) red[tid] = 0.0f;
        __syncthreads();
#pragma unroll
        for (int mt = 0; mt < MT; mt++) {
            float pA = 0.0f, pB = 0.0f;
#pragma unroll
            for (int nt = 0; nt < 4; nt++) {
                int col = bn + wn0 + nt * 8 + (lane & 3) * 2;
                float2 bs = *(const float2*)(bias + col);
                float w0 = aux1[col], w1 = aux1[col + 1];
                pA += gelu_exact(c[mt][nt][0] + bs.x) * w0
                    + gelu_exact(c[mt][nt][1] + bs.y) * w1;
                pB += gelu_exact(c[mt][nt][2] + bs.x) * w0
                    + gelu_exact(c[mt][nt][3] + bs.y) * w1;
            }
            pA += __shfl_xor_sync(0xffffffffu, pA, 1);
            pA += __shfl_xor_sync(0xffffffffu, pA, 2);
            pB += __shfl_xor_sync(0xffffffffu, pB, 1);
            pB += __shfl_xor_sync(0xffffffffu, pB, 2);
            if ((lane & 3) == 0) {
                int rA = wm0 + mt * 16 + (lane >> 2);
                atomicAdd(&red[rA], pA);
                atomicAdd(&red[rA + 8], pB);
            }
        }
        __syncthreads();
        if (tid < TM)
            Cm[bm + tid] = 1.0f / (1.0f + __expf(-(red[tid] + aux2[0])));
        return;
    }

    if (EPI == 3) {
        constexpr int SROW = TM + 8;
        float* stage = (float*)smem;
        __syncthreads();
#pragma unroll
        for (int mt = 0; mt < MT; mt++) {
            const int row = wm0 + mt * 16 + (lane >> 2);
#pragma unroll
            for (int nt = 0; nt < 4; nt++) {
                const int col = wn0 + nt * 8 + (lane & 3) * 2;
                float2 bs = *(const float2*)(bias + bn + col);
                stage[col*SROW + row]           = c[mt][nt][0] + bs.x;
                stage[(col+1)*SROW + row]       = c[mt][nt][1] + bs.y;
                stage[col*SROW + row + 8]       = c[mt][nt][2] + bs.x;
                stage[(col+1)*SROW + row + 8]   = c[mt][nt][3] + bs.y;
            }
        }
        __syncthreads();
        const int bloc = bm >> 10, l0 = bm & (LL - 1);
        // 128 l per CTA: full warp of float4 per c-row (MT=4 path)
        float4 mk = *(const float4*)(aux1 + bm + lane * 4);
#pragma unroll
        for (int g = 0; g < 4; g++) {
            size_t oo[4];
            float4 xw[4];
#pragma unroll
            for (int j = 0; j < 4; j++) {
                int cr = wid + (g * 4 + j) * 8;
                oo[j] = ((size_t)(bloc*CC + bn + cr)) * LL + l0 + lane*4;
                xw[j] = *(const float4*)(aux2 + oo[j]);
            }
#pragma unroll
            for (int j = 0; j < 4; j++) {
                int cr = wid + (g * 4 + j) * 8;
                float4 vv = *(const float4*)&stage[cr*SROW + lane*4];
                float4 r;
                r.x = xw[j].x + mk.x * vv.x;
                r.y = xw[j].y + mk.y * vv.y;
                r.z = xw[j].z + mk.z * vv.z;
                r.w = xw[j].w + mk.w * vv.w;
                stcs4(Cm + oo[j], r);
            }
        }
        return;
    }
}

// ---- fused launch: QKV GEMM (768 CTAs, MT=4) + detector (128 CTAs) ---------
#define QKV_BLOCKS 768
#define FUSED_SMEM (3 * (128*128 + 16384))   // 98304
__global__ void __launch_bounds__(256, 2)
fused_qkv_det(const __nv_bfloat16* __restrict__ comb,
              const __nv_bfloat16* __restrict__ ipw,
              const float* __restrict__ ipb,
              __nv_bfloat16* __restrict__ qkv,
              const __nv_bfloat16* __restrict__ w1,
              const float* __restrict__ det_b1,
              const float* __restrict__ det_w2,
              const float* __restrict__ det_b2,
              float* __restrict__ mask)
{
    extern __shared__ char smem[];
    int bx = blockIdx.x;
    if (bx < QKV_BLOCKS) {
        int bn = (bx % 12) * 128;
        int bm = (bx / 12) * 128;
        gemm_body<1,4>(bm, bn, comb + CC, 2*CC, ipw, CC, ipb,
                       (float*)qkv, 3*CC, CC, nullptr, nullptr, smem);
    } else {
        int bm = (bx - QKV_BLOCKS) * 64;
        gemm_body<2,2>(bm, 0, comb, 2*CC, w1, 2*CC, det_b1,
                       mask, 1, 2*CC, det_w2, det_b2, smem);
    }
}

// ---- out_proj GEMM fused with gated combine: MT=4 (R14 optimum) ------------
__global__ void __launch_bounds__(256, 2)
outproj_combine(const __nv_bfloat16* __restrict__ ctx,
                const __nv_bfloat16* __restrict__ opw,
                const float* __restrict__ opb,
                float* __restrict__ out,
                const float* __restrict__ mask,
                const float* __restrict__ xwalze)
{
    extern __shared__ char smem[];
    gemm_body<3,4>(blockIdx.y * 128, blockIdx.x * 128, ctx, CC, opw, CC,
                   opb, out, 0, CC, mask, xwalze, smem);
}

// ==== fused walze: full-plane conv/BN/GELU + comb pack + xwalze, 1 launch ====
#define WCH 8
#define WPAD 1028
#define WALZE_PLANES 512                            // 8 b x 64 ct
#define RW_TOTAL (3*CC*CC + CC*CC + 128*2*CC)       // 1,179,648
#define RW_BLOCKS ((RW_TOTAL + 255)/256)            // 4608
#define WALZE_SMEM ((WCH*WPAD + WCH*136) * 4)       // 37248 B

__global__ void __launch_bounds__(256)
walze_fused(const float* __restrict__ x,
            const float* __restrict__ dw_w,
            const float* __restrict__ dw_b,
            const float* __restrict__ sh_w,
            const float* __restrict__ sh_b,
            const float* __restrict__ mixw,
            const float* __restrict__ gamma,
            const float* __restrict__ beta,
            const float* __restrict__ ipw,
            const float* __restrict__ opw,
            const float* __restrict__ w1)
{
    int bi = blockIdx.x;
    int tid = threadIdx.x;
    if (bi >= WALZE_PLANES) {
        int i = (bi - WALZE_PLANES) * 256 + tid;
        const int N1 = 3*CC*CC, N2 = CC*CC, N3 = 128*2*CC;
        if (i < N1)                 g_ipw[i] = __float2bfloat16_rn(ipw[i]);
        else if (i < N1 + N2)       g_opw[i - N1] = __float2bfloat16_rn(opw[i - N1]);
        else if (i < N1 + N2 + N3)  g_w1[i - N1 - N2] = __float2bfloat16_rn(w1[i - N1 - N2]);
        return;
    }
    extern __shared__ float sx[];            // [WCH][WPAD]
    float* swo = sx + WCH * WPAD;            // [WCH][136]

    int ct = bi & 63, b = bi >> 6;
    int c0 = ct * WCH;

    for (int i = tid; i < WCH * 256; i += 256) {
        int c = i >> 8, l4 = (i & 255) * 4;
        float4 v = *(const float4*)(x + ((size_t)(b*CC + c0 + c)) * LL + l4);
        *(float4*)(sx + c * WPAD + l4) = v;
    }
    __syncthreads();

    const int c = tid & 7;
    const int lb = tid >> 3;                 // 0..31
    const float* dk = dw_w + (c0 + c) * 9;
    float d0 = dk[0], d1 = dk[1], d2 = dk[2], d3 = dk[3], d4 = dk[4],
          d5 = dk[5], d6 = dk[6], d7 = dk[7], d8 = dk[8];
    float dwb = dw_b[c0 + c];
    float gm = gamma[c0 + c] * rsqrtf(1.0f + 1e-5f);
    float bt = beta[c0 + c];
    float s0 = sh_w[0], s1 = sh_w[1], s2 = sh_w[2], s3 = sh_w[3], s4 = sh_w[4],
          s5 = sh_w[5], s6 = sh_w[6], s7 = sh_w[7], s8 = sh_w[8];
    float shb = sh_b[0];
    float mix = 1.0f / (1.0f + __expf(-mixw[0]));
    const float* row = sx + c * WPAD;

    for (int k = 0; k < 8; k++) {
#pragma unroll
        for (int j = 0; j < 4; j++) {
            int ll = lb + 32 * j;            // 0..127 within slab
            int l = k * 128 + ll;
            int h = l >> 5, w = l & 31;
            int hm = (h + 31) & 31, hp = (h + 1) & 31;
            int wm = (w + 31) & 31, wp = (w + 1) & 31;
            float v00 = row[hm*32+wm], v01 = row[hm*32+w], v02 = row[hm*32+wp];
            float v10 = row[h*32+wm],  v11 = row[h*32+w],  v12 = row[h*32+wp];
            float v20 = row[hp*32+wm], v21 = row[hp*32+w], v22 = row[hp*32+wp];
            float mo = v00*d0 + v01*d1 + v02*d2 + v10*d3 + v11*d4 + v12*d5
                     + v20*d6 + v21*d7 + v22*d8 + dwb;
            float ex = v00*s0 + v01*s1 + v02*s2 + v10*s3 + v11*s4 + v12*s5
                     + v20*s6 + v21*s7 + v22*s8 + shb;
            float xw = gelu_exact(gm * (mix*mo + (1.0f-mix)*ex + v11) + bt);
            size_t dst = ((size_t)(b*LL + l)) * (2*CC) + c0 + c;
            g_comb[dst]      = __float2bfloat16_rn(v11);
            g_comb[dst + CC] = __float2bfloat16_rn(xw);
            swo[c * 136 + ll] = xw;
        }
        __syncthreads();
#pragma unroll
        for (int j = 0; j < 4; j++) {
            int idx = tid + 256 * j;         // 0..1023
            int c2 = idx >> 7, l2 = idx & 127;
            g_xwalze[((size_t)(b*CC + c0 + c2)) * LL + k*128 + l2] =
                swo[c2 * 136 + l2];
        }
        __syncthreads();
    }
}

// ============ banded attention via mma: S = QK^T, ctx = P V =================
#define ATT_VT  0                        // 64 x 208
#define ATT_LS  (ATT_VT + 64*208)        // 13312, 64 floats
#define ATT_Q   (ATT_LS + 256)           // 13568, 64 x 144
#define ATT_K   (ATT_Q + 64*144)         // 22784, 96 x 144
#define ATT_P   ATT_Q                    // aliases Q/K (needs 64*208 <= 23040)
#define ATT_SMEM (ATT_K + 96*144)        // 36608

__global__ void __launch_bounds__(256, 4)
attn_kernel()
{
    extern __shared__ char smem[];
    const uint32_t sb = smem_u32(smem);
    int bi = blockIdx.x;
    int qt = bi & 15, h = (bi >> 4) & 7, b = bi >> 7;
    int q0 = qt * 64;
    int jlo = max(0, q0 - WHALF);
    int jhi = min(LL - 1, q0 + 63 + WHALF);
    int nrows = jhi - jlo + 1;              // 80 or 96
    int tid = threadIdx.x, lane = tid & 31, wid = tid >> 5;

    const __nv_bfloat16* qb = g_qkv + (size_t)(b*LL + q0) * (3*CC) + h*HD;
    for (int i = tid; i < 64*8; i += 256) {
        int r = i >> 3, cb = (i & 7) * 16;
        uint4 v = *(const uint4*)((const char*)(qb + (size_t)r * (3*CC)) + cb);
        *(uint4*)(smem + ATT_Q + r*144 + cb) = v;
    }
    const __nv_bfloat16* kb = g_qkv + (size_t)(b*LL + jlo) * (3*CC) + CC + h*HD;
    for (int i = tid; i < 96*8; i += 256) {
        int r = i >> 3, cb = (i & 7) * 16;
        uint4 v = make_uint4(0u, 0u, 0u, 0u);
        if (r < nrows)
            v = *(const uint4*)((const char*)(kb + (size_t)r * (3*CC)) + cb);
        *(uint4*)(smem + ATT_K + r*144 + cb) = v;
    }
    const __nv_bfloat16* vb = kb + CC;
    for (int i = tid; i < 96*16; i += 256) {
        int r = i >> 4, c4 = (i & 15) * 4;
        uint2 v = make_uint2(0u, 0u);
        if (r < nrows)
            v = *(const uint2*)(vb + (size_t)r * (3*CC) + c4);
        const __nv_bfloat16* hv = (const __nv_bfloat16*)&v;
        *(__nv_bfloat16*)(smem + ATT_VT + (c4+0)*208 + r*2) = hv[0];
        *(__nv_bfloat16*)(smem + ATT_VT + (c4+1)*208 + r*2) = hv[1];
        *(__nv_bfloat16*)(smem + ATT_VT + (c4+2)*208 + r*2) = hv[2];
        *(__nv_bfloat16*)(smem + ATT_VT + (c4+3)*208 + r*2) = hv[3];
    }
    if (tid < 64) ((float*)(smem + ATT_LS))[tid] = 0.0f;
    __syncthreads();

    const int wm0 = (wid & 1) * 32;
    const int wn0s = (wid >> 1) * 24;
    float s[2][3][4];
#pragma unroll
    for (int i = 0; i < 2; i++)
#pragma unroll
        for (int j = 0; j < 3; j++)
#pragma unroll
            for (int k = 0; k < 4; k++) s[i][j][k] = 0.0f;
    {
        const uint32_t aAddr = sb + ATT_Q + (uint32_t)((wm0 + (lane & 15)) * 144)
                             + ((uint32_t)(lane >> 4) << 4);
        const uint32_t bAddr4 = sb + ATT_K
                             + (uint32_t)((wn0s + ((lane >> 4) << 3) + (lane & 7)) * 144)
                             + (uint32_t)(((lane >> 3) & 1) << 4);
        const uint32_t bAddr2 = sb + ATT_K
                             + (uint32_t)((wn0s + 16 + (lane & 7)) * 144)
                             + (uint32_t)(((lane >> 3) & 1) << 4);
#pragma unroll
        for (int ks = 0; ks < 4; ks++) {
            const uint32_t kso = (uint32_t)(ks * 32);
            uint32_t a0[4], a1[4], bb[3][2];
            ldmx4(aAddr + kso,            a0[0], a0[1], a0[2], a0[3]);
            ldmx4(aAddr + 16*144 + kso,   a1[0], a1[1], a1[2], a1[3]);
            ldmx4(bAddr4 + kso, bb[0][0], bb[0][1], bb[1][0], bb[1][1]);
            ldmx2(bAddr2 + kso, bb[2][0], bb[2][1]);
#pragma unroll
            for (int nt = 0; nt < 3; nt++) {
                mma16(s[0][nt], a0[0], a0[1], a0[2], a0[3], bb[nt][0], bb[nt][1]);
                mma16(s[1][nt], a1[0], a1[1], a1[2], a1[3], bb[nt][0], bb[nt][1]);
            }
        }
    }
    __syncthreads();   // Q/K reads complete before P overwrites that region

    float* lsum = (float*)(smem + ATT_LS);
#pragma unroll
    for (int mt = 0; mt < 2; mt++) {
        int row = wm0 + mt * 16 + (lane >> 2);
        int qA = q0 + row, qB = qA + 8;
        float rs0 = 0.0f, rs1 = 0.0f;
#pragma unroll
        for (int nt = 0; nt < 3; nt++) {
            int col = wn0s + nt * 8 + (lane & 3) * 2;
            int gj0 = jlo + col, gj1 = gj0 + 1;
            bool a00 = (gj0 >= qA - WHALF) && (gj0 <= qA + WHALF) && (gj0 < LL);
            bool a01 = (gj1 >= qA - WHALF) && (gj1 <= qA + WHALF) && (gj1 < LL);
            bool a10 = (gj0 >= qB - WHALF) && (gj0 <= qB + WHALF) && (gj0 < LL);
            bool a11 = (gj1 >= qB - WHALF) && (gj1 <= qB + WHALF) && (gj1 < LL);
            float p00 = a00 ? __expf(s[mt][nt][0]) : 0.0f;
            float p01 = a01 ? __expf(s[mt][nt][1]) : 0.0f;
            float p10 = a10 ? __expf(s[mt][nt][2]) : 0.0f;
            float p11 = a11 ? __expf(s[mt][nt][3]) : 0.0f;
            rs0 += p00 + p01; rs1 += p10 + p11;
            *(uint32_t*)(smem + ATT_P + row*208 + col*2)     = bf2pack(p00, p01);
            *(uint32_t*)(smem + ATT_P + (row+8)*208 + col*2) = bf2pack(p10, p11);
        }
        rs0 += __shfl_xor_sync(0xffffffffu, rs0, 1);
        rs0 += __shfl_xor_sync(0xffffffffu, rs0, 2);
        rs1 += __shfl_xor_sync(0xffffffffu, rs1, 1);
        rs1 += __shfl_xor_sync(0xffffffffu, rs1, 2);
        if ((lane & 3) == 0) {
            atomicAdd(&lsum[row], rs0);
            atomicAdd(&lsum[row + 8], rs1);
        }
    }
    __syncthreads();

    const int wn0v = (wid >> 1) * 16;
    float o[2][2][4];
#pragma unroll
    for (int i = 0; i < 2; i++)
#pragma unroll
        for (int j = 0; j < 2; j++)
#pragma unroll
            for (int k = 0; k < 4; k++) o[i][j][k] = 0.0f;
    {
        const uint32_t aAddr = sb + ATT_P + (uint32_t)((wm0 + (lane & 15)) * 208)
                             + ((uint32_t)(lane >> 4) << 4);
        const uint32_t bAddr = sb + ATT_VT
                             + (uint32_t)((wn0v + ((lane >> 4) << 3) + (lane & 7)) * 208)
                             + (uint32_t)(((lane >> 3) & 1) << 4);
#pragma unroll
        for (int ks = 0; ks < 6; ks++) {
            const uint32_t kso = (uint32_t)(ks * 32);
            uint32_t a0[4], a1[4], bb[2][2];
            ldmx4(aAddr + kso,          a0[0], a0[1], a0[2], a0[3]);
            ldmx4(aAddr + 16*208 + kso, a1[0], a1[1], a1[2], a1[3]);
            ldmx4(bAddr + kso, bb[0][0], bb[0][1], bb[1][0], bb[1][1]);
#pragma unroll
            for (int nt = 0; nt < 2; nt++) {
                mma16(o[0][nt], a0[0], a0[1], a0[2], a0[3], bb[nt][0], bb[nt][1]);
                mma16(o[1][nt], a1[0], a1[1], a1[2], a1[3], bb[nt][0], bb[nt][1]);
            }
        }
    }

#pragma unroll
    for (int mt = 0; mt < 2; mt++) {
        int row = wm0 + mt * 16 + (lane >> 2);
        float inv0 = 1.0f / lsum[row];
        float inv1 = 1.0f / lsum[row + 8];
#pragma unroll
        for (int nt = 0; nt < 2; nt++) {
            int col = wn0v + nt * 8 + (lane & 3) * 2;
            __nv_bfloat16* d0 = g_ctx + (size_t)(b*LL + q0 + row) * CC + h*HD + col;
            __nv_bfloat16* d1 = d0 + (size_t)8 * CC;
            *(uint32_t*)d0 = bf2pack(o[mt][nt][0] * inv0, o[mt][nt][1] * inv0);
            *(uint32_t*)d1 = bf2pack(o[mt][nt][2] * inv1, o[mt][nt][3] * inv1);
        }
    }
}

// ---------------- host launcher ---------------------------------------------
extern "C" void kernel_launch(void* const* d_in, const int* in_sizes, int n_in,
                              void* d_out, int out_size)
{
    const float* x      = (const float*)d_in[0];
    const float* dw_w   = (const float*)d_in[1];
    const float* dw_b   = (const float*)d_in[2];
    const float* sh_w   = (const float*)d_in[3];
    const float* sh_b   = (const float*)d_in[4];
    const float* mixw   = (const float*)d_in[5];
    const float* gamma  = (const float*)d_in[6];
    const float* beta   = (const float*)d_in[7];
    const float* det_w1 = (const float*)d_in[8];
    const float* det_b1 = (const float*)d_in[9];
    const float* det_w2 = (const float*)d_in[10];
    const float* det_b2 = (const float*)d_in[11];
    const float* ipw    = (const float*)d_in[12];
    const float* ipb    = (const float*)d_in[13];
    const float* opw    = (const float*)d_in[14];
    const float* opb    = (const float*)d_in[15];
    float* out = (float*)d_out;

    __nv_bfloat16 *p_comb, *p_ctx, *p_ipw, *p_opw, *p_w1, *p_qkv;
    float *p_mask, *p_xwalze;
    cudaGetSymbolAddress((void**)&p_comb,    g_comb);
    cudaGetSymbolAddress((void**)&p_qkv,     g_qkv);
    cudaGetSymbolAddress((void**)&p_ctx,     g_ctx);
    cudaGetSymbolAddress((void**)&p_ipw,     g_ipw);
    cudaGetSymbolAddress((void**)&p_opw,     g_opw);
    cudaGetSymbolAddress((void**)&p_w1,      g_w1);
    cudaGetSymbolAddress((void**)&p_mask,    g_mask);
    cudaGetSymbolAddress((void**)&p_xwalze,  g_xwalze);

    cudaFuncSetAttribute((const void*)fused_qkv_det,
                         cudaFuncAttributeMaxDynamicSharedMemorySize, FUSED_SMEM);
    cudaFuncSetAttribute((const void*)outproj_combine,
                         cudaFuncAttributeMaxDynamicSharedMemorySize, FUSED_SMEM);
    cudaFuncSetAttribute((const void*)attn_kernel,
                         cudaFuncAttributeMaxDynamicSharedMemorySize, ATT_SMEM);
    cudaFuncSetAttribute((const void*)walze_fused,
                         cudaFuncAttributeMaxDynamicSharedMemorySize, WALZE_SMEM);

    // 1) fused walze: conv/BN/GELU + comb pack + xwalze (+ weight rounding tail)
    walze_fused<<<WALZE_PLANES + RW_BLOCKS, 256, WALZE_SMEM>>>(
        x, dw_w, dw_b, sh_w, sh_b, mixw, gamma, beta, ipw, opw, det_w1);

    // 2) fused QKV GEMM (bf16 out, Q pre-scaled) + detector GEMM/head
    fused_qkv_det<<<QKV_BLOCKS + 128, 256, FUSED_SMEM>>>(
        p_comb, p_ipw, ipb, p_qkv, p_w1, det_b1, det_w2, det_b2, p_mask);

    // 3) banded attention (mma-based, bf16 I/O, 4 CTAs/SM target)
    attn_kernel<<<BB*NHD*(LL/64), 256, ATT_SMEM>>>();

    // 4) out_proj GEMM fused with gated combine: MT=4 (R14 optimum) -> out
    {
        dim3 g(CC/128, (BB*LL)/128);
        outproj_combine<<<g, 256, FUSED_SMEM>>>(p_ctx, p_opw, opb, out,
                                                p_mask, p_xwalze);
    }
}

// round 17
// speedup vs baseline: 1.0302x; 1.0076x over previous
#include <cuda_runtime.h>
#include <cuda_bf16.h>
#include <math.h>
#include <stdint.h>

#define BB 8
#define CC 512
#define HH 32
#define WW 32
#define LL 1024   // H*W
#define NHD 8
#define HD 64
#define WHALF 16  // WINDOW/2

// ---------------- scratch (static device globals; no runtime allocation) ----
__device__ float g_xwalze[BB*CC*HH*WW];          // (B,C,H,W) post-walze
__device__ __nv_bfloat16 g_comb[BB*LL*2*CC];     // (B*L, 2C): [before | after]
__device__ float g_mask[BB*LL];                  // soft mask
__device__ __nv_bfloat16 g_qkv[BB*LL*3*CC];      // (B*L, 3C) bf16, Q pre-scaled
__device__ __nv_bfloat16 g_ctx[BB*LL*CC];        // attention context (bf16)
__device__ __nv_bfloat16 g_ipw[3*CC*CC];         // bf16 in_proj_w
__device__ __nv_bfloat16 g_opw[CC*CC];           // bf16 out_proj_w
__device__ __nv_bfloat16 g_w1[128*2*CC];         // bf16 det_w1

__device__ __forceinline__ float gelu_exact(float v) {
    return 0.5f * v * (1.0f + erff(v * 0.70710678118654752440f));
}
__device__ __forceinline__ uint32_t smem_u32(const void* p) {
    uint32_t a;
    asm("{ .reg .u64 t; cvta.to.shared.u64 t, %1; cvt.u32.u64 %0, t; }"
        : "=r"(a) : "l"(p));
    return a;
}
__device__ __forceinline__ void cp16(uint32_t dst, const void* src) {
    asm volatile("cp.async.cg.shared.global [%0], [%1], 16;" :: "r"(dst), "l"(src));
}
__device__ __forceinline__ void ldmx4(uint32_t addr, uint32_t& r0, uint32_t& r1,
                                      uint32_t& r2, uint32_t& r3) {
    asm volatile("ldmatrix.sync.aligned.m8n8.x4.shared.b16 {%0,%1,%2,%3}, [%4];"
                 : "=r"(r0), "=r"(r1), "=r"(r2), "=r"(r3) : "r"(addr));
}
__device__ __forceinline__ void ldmx2(uint32_t addr, uint32_t& r0, uint32_t& r1) {
    asm volatile("ldmatrix.sync.aligned.m8n8.x2.shared.b16 {%0,%1}, [%2];"
                 : "=r"(r0), "=r"(r1) : "r"(addr));
}
__device__ __forceinline__ void mma16(float* c, uint32_t a0, uint32_t a1,
                                      uint32_t a2, uint32_t a3,
                                      uint32_t b0, uint32_t b1) {
    asm volatile("mma.sync.aligned.m16n8k16.row.col.f32.bf16.bf16.f32 "
                 "{%0,%1,%2,%3}, {%4,%5,%6,%7}, {%8,%9}, {%0,%1,%2,%3};"
                 : "+f"(c[0]), "+f"(c[1]), "+f"(c[2]), "+f"(c[3])
                 : "r"(a0), "r"(a1), "r"(a2), "r"(a3), "r"(b0), "r"(b1));
}
__device__ __forceinline__ uint32_t bf2pack(float a, float b) {
    __nv_bfloat162 t = __floats2bfloat162_rn(a, b);
    return *(uint32_t*)&t;
}
__device__ __forceinline__ void stcs4(float* p, float4 v) {
    asm volatile("st.global.cs.v4.f32 [%0], {%1,%2,%3,%4};"
                 :: "l"(p), "f"(v.x), "f"(v.y), "f"(v.z), "f"(v.w) : "memory");
}
__device__ __forceinline__ float4 ldcs4(const float* p) {
    float4 v;
    asm volatile("ld.global.cs.v4.f32 {%0,%1,%2,%3}, [%4];"
                 : "=f"(v.x), "=f"(v.y), "=f"(v.z), "=f"(v.w) : "l"(p));
    return v;
}

// ====== bf16 mma.sync GEMM body (validated) =================================
// EPI: 1 = bf16 store with Q-column 0.125 scaling, 2 = detector head,
//      3 = fused gated combine (smem-staged coalesced, pipelined xw loads).
template<int EPI, int MT>
__device__ __forceinline__ void
gemm_body(int bm, int bn,
          const __nv_bfloat16* __restrict__ A, int lda,
          const __nv_bfloat16* __restrict__ Bm, int ldb,
          const float* __restrict__ bias,
          float* __restrict__ Cm, int ldc, int K,
          const float* __restrict__ aux1,   // EPI2: w2    EPI3: mask
          const float* __restrict__ aux2,   // EPI2: b2    EPI3: xwalze
          char* smem)
{
    constexpr int TM = MT * 32;
    constexpr int ABYTES = TM * 128;
    constexpr int BUFB = ABYTES + 16384;
    const uint32_t sb = smem_u32(smem);
    const int tid = threadIdx.x, lane = tid & 31, wid = tid >> 5;
    const int wm0 = (wid & 1) * (TM / 2), wn0 = (wid >> 1) * 32;

    const int ld_row = tid >> 3;
    const uint32_t st_off =
        (uint32_t)(ld_row * 128 + (((tid & 7) * 16) ^ ((ld_row & 7) << 4)));
    const __nv_bfloat16* Agb = A  + (size_t)(bm + ld_row) * lda + (tid & 7) * 8;
    const __nv_bfloat16* Bgb = Bm + (size_t)(bn + ld_row) * ldb + (tid & 7) * 8;

    auto load_tile = [&](int buf, int ch) {
        uint32_t da = sb + buf * BUFB + st_off;
        uint32_t db = da + ABYTES;
        const __nv_bfloat16* sa  = Agb + ch * 64;
        const __nv_bfloat16* sbp = Bgb + ch * 64;
#pragma unroll
        for (int p = 0; p < MT; p++)
            cp16(da + p * 4096, sa + (size_t)p * 32 * lda);
#pragma unroll
        for (int p = 0; p < 4; p++)
            cp16(db + p * 4096, sbp + (size_t)p * 32 * ldb);
        asm volatile("cp.async.commit_group;" ::: "memory");
    };

    const int arow  = wm0 + (lane & 15);
    const uint32_t akb = ((uint32_t)(lane >> 4)) << 4;
    const uint32_t aswz = (uint32_t)((arow & 7) << 4);
    const uint32_t a_rowbase = (uint32_t)(arow * 128);
    const int brow  = wn0 + ((lane >> 4) << 3) + (lane & 7);
    const uint32_t bkb = (uint32_t)(((lane >> 3) & 1) << 4);
    const uint32_t bswz = (uint32_t)((brow & 7) << 4);
    const uint32_t b_rowbase = (uint32_t)(ABYTES + brow * 128);

    float c[MT][4][4];
#pragma unroll
    for (int i = 0; i < MT; i++)
#pragma unroll
        for (int j = 0; j < 4; j++)
#pragma unroll
            for (int k = 0; k < 4; k++) c[i][j][k] = 0.0f;

    const int nch = K >> 6;
    load_tile(0, 0);
    load_tile(1, 1);

    for (int ch = 0; ch < nch; ch++) {
        const int buf = ch % 3;
        if (ch + 1 < nch) asm volatile("cp.async.wait_group 1;" ::: "memory");
        else              asm volatile("cp.async.wait_group 0;" ::: "memory");
        __syncthreads();
        if (ch + 2 < nch) load_tile((ch + 2) % 3, ch + 2);

        const uint32_t base = sb + buf * BUFB;
#pragma unroll
        for (int ks = 0; ks < 4; ks++) {
            const uint32_t kso = (uint32_t)(ks * 32);
            uint32_t a[MT][4];
#pragma unroll
            for (int mt = 0; mt < MT; mt++)
                ldmx4(base + a_rowbase + (uint32_t)(mt * 2048) + ((kso + akb) ^ aswz),
                      a[mt][0], a[mt][1], a[mt][2], a[mt][3]);
            uint32_t b[4][2];
#pragma unroll
            for (int nt2 = 0; nt2 < 2; nt2++)
                ldmx4(base + b_rowbase + (uint32_t)(nt2 * 2048) + ((kso + bkb) ^ bswz),
                      b[nt2*2][0], b[nt2*2][1], b[nt2*2+1][0], b[nt2*2+1][1]);
#pragma unroll
            for (int mt = 0; mt < MT; mt++)
#pragma unroll
                for (int nt = 0; nt < 4; nt++)
                    mma16(c[mt][nt], a[mt][0], a[mt][1], a[mt][2], a[mt][3],
                          b[nt][0], b[nt][1]);
        }
    }

    if (EPI == 1) {
        __nv_bfloat16* Cb = (__nv_bfloat16*)Cm;
#pragma unroll
        for (int mt = 0; mt < MT; mt++) {
            const int r0 = bm + wm0 + mt * 16 + (lane >> 2);
#pragma unroll
            for (int nt = 0; nt < 4; nt++) {
                const int col = bn + wn0 + nt * 8 + (lane & 3) * 2;
                float2 bs = *(const float2*)(bias + col);
                float sc = (col < 512) ? 0.125f : 1.0f;
                float v0 = (c[mt][nt][0] + bs.x) * sc;
                float v1 = (c[mt][nt][1] + bs.y) * sc;
                float v2 = (c[mt][nt][2] + bs.x) * sc;
                float v3 = (c[mt][nt][3] + bs.y) * sc;
                *(uint32_t*)(Cb + (size_t)r0 * ldc + col)       = bf2pack(v0, v1);
                *(uint32_t*)(Cb + (size_t)(r0 + 8) * ldc + col) = bf2pack(v2, v3);
            }
        }
        return;
    }

    if (EPI == 2) {
        float* red = (float*)smem;
        __syncthreads();
        if (tid < TM) red[tid] = 0.0f;
        __syncthreads();
#pragma unroll
        for (int mt = 0; mt < MT; mt++) {
            float pA = 0.0f, pB = 0.0f;
#pragma unroll
            for (int nt = 0; nt < 4; nt++) {
                int col = bn + wn0 + nt * 8 + (lane & 3) * 2;
                float2 bs = *(const float2*)(bias + col);
                float w0 = aux1[col], w1 = aux1[col + 1];
                pA += gelu_exact(c[mt][nt][0] + bs.x) * w0
                    + gelu_exact(c[mt][nt][1] + bs.y) * w1;
                pB += gelu_exact(c[mt][nt][2] + bs.x) * w0
                    + gelu_exact(c[mt][nt][3] + bs.y) * w1;
            }
            pA += __shfl_xor_sync(0xffffffffu, pA, 1);
            pA += __shfl_xor_sync(0xffffffffu, pA, 2);
            pB += __shfl_xor_sync(0xffffffffu, pB, 1);
            pB += __shfl_xor_sync(0xffffffffu, pB, 2);
            if ((lane & 3) == 0) {
                int rA = wm0 + mt * 16 + (lane >> 2);
                atomicAdd(&red[rA], pA);
                atomicAdd(&red[rA + 8], pB);
            }
        }
        __syncthreads();
        if (tid < TM)
            Cm[bm + tid] = 1.0f / (1.0f + __expf(-(red[tid] + aux2[0])));
        return;
    }

    if (EPI == 3) {
        constexpr int SROW = TM + 8;
        float* stage = (float*)smem;
        const int bloc = bm >> 10, l0 = bm & (LL - 1);
        // issue group-0 xwalze loads early (addresses independent of stage)
        size_t oo[4];
        float4 xw[4];
#pragma unroll
        for (int j = 0; j < 4; j++) {
            int cr = wid + j * 8;
            oo[j] = ((size_t)(bloc*CC + bn + cr)) * LL + l0 + lane*4;
            xw[j] = ldcs4(aux2 + oo[j]);
        }
        __syncthreads();
#pragma unroll
        for (int mt = 0; mt < MT; mt++) {
            const int row = wm0 + mt * 16 + (lane >> 2);
#pragma unroll
            for (int nt = 0; nt < 4; nt++) {
                const int col = wn0 + nt * 8 + (lane & 3) * 2;
                float2 bs = *(const float2*)(bias + bn + col);
                stage[col*SROW + row]           = c[mt][nt][0] + bs.x;
                stage[(col+1)*SROW + row]       = c[mt][nt][1] + bs.y;
                stage[col*SROW + row + 8]       = c[mt][nt][2] + bs.x;
                stage[(col+1)*SROW + row + 8]   = c[mt][nt][3] + bs.y;
            }
        }
        __syncthreads();
        float4 mk = *(const float4*)(aux1 + bm + lane * 4);
#pragma unroll
        for (int g = 0; g < 4; g++) {
            size_t noo[4];
            float4 nxw[4];
            if (g + 1 < 4) {
                // prefetch next group's xwalze loads
#pragma unroll
                for (int j = 0; j < 4; j++) {
                    int cr = wid + ((g + 1) * 4 + j) * 8;
                    noo[j] = ((size_t)(bloc*CC + bn + cr)) * LL + l0 + lane*4;
                    nxw[j] = ldcs4(aux2 + noo[j]);
                }
            }
#pragma unroll
            for (int j = 0; j < 4; j++) {
                int cr = wid + (g * 4 + j) * 8;
                float4 vv = *(const float4*)&stage[cr*SROW + lane*4];
                float4 r;
                r.x = xw[j].x + mk.x * vv.x;
                r.y = xw[j].y + mk.y * vv.y;
                r.z = xw[j].z + mk.z * vv.z;
                r.w = xw[j].w + mk.w * vv.w;
                stcs4(Cm + oo[j], r);
            }
            if (g + 1 < 4) {
#pragma unroll
                for (int j = 0; j < 4; j++) { oo[j] = noo[j]; xw[j] = nxw[j]; }
            }
        }
        return;
    }
}

// ---- fused launch: QKV GEMM (768 CTAs, MT=4) + detector (128 CTAs) ---------
#define QKV_BLOCKS 768
#define FUSED_SMEM (3 * (128*128 + 16384))   // 98304
__global__ void __launch_bounds__(256, 2)
fused_qkv_det(const __nv_bfloat16* __restrict__ comb,
              const __nv_bfloat16* __restrict__ ipw,
              const float* __restrict__ ipb,
              __nv_bfloat16* __restrict__ qkv,
              const __nv_bfloat16* __restrict__ w1,
              const float* __restrict__ det_b1,
              const float* __restrict__ det_w2,
              const float* __restrict__ det_b2,
              float* __restrict__ mask)
{
    extern __shared__ char smem[];
    int bx = blockIdx.x;
    if (bx < QKV_BLOCKS) {
        int bn = (bx % 12) * 128;
        int bm = (bx / 12) * 128;
        gemm_body<1,4>(bm, bn, comb + CC, 2*CC, ipw, CC, ipb,
                       (float*)qkv, 3*CC, CC, nullptr, nullptr, smem);
    } else {
        int bm = (bx - QKV_BLOCKS) * 64;
        gemm_body<2,2>(bm, 0, comb, 2*CC, w1, 2*CC, det_b1,
                       mask, 1, 2*CC, det_w2, det_b2, smem);
    }
}

// ---- out_proj GEMM fused with gated combine: MT=4 (R14/R16 optimum) --------
__global__ void __launch_bounds__(256, 2)
outproj_combine(const __nv_bfloat16* __restrict__ ctx,
                const __nv_bfloat16* __restrict__ opw,
                const float* __restrict__ opb,
                float* __restrict__ out,
                const float* __restrict__ mask,
                const float* __restrict__ xwalze)
{
    extern __shared__ char smem[];
    gemm_body<3,4>(blockIdx.y * 128, blockIdx.x * 128, ctx, CC, opw, CC,
                   opb, out, 0, CC, mask, xwalze, smem);
}

// ==== fused walze: full-plane conv/BN/GELU + comb pack + xwalze, 1 launch ====
#define WCH 8
#define WPAD 1028
#define WALZE_PLANES 512                            // 8 b x 64 ct
#define RW_TOTAL (3*CC*CC + CC*CC + 128*2*CC)       // 1,179,648
#define RW_BLOCKS ((RW_TOTAL + 255)/256)            // 4608
#define WALZE_SMEM ((WCH*WPAD + WCH*136) * 4)       // 37248 B

__global__ void __launch_bounds__(256)
walze_fused(const float* __restrict__ x,
            const float* __restrict__ dw_w,
            const float* __restrict__ dw_b,
            const float* __restrict__ sh_w,
            const float* __restrict__ sh_b,
            const float* __restrict__ mixw,
            const float* __restrict__ gamma,
            const float* __restrict__ beta,
            const float* __restrict__ ipw,
            const float* __restrict__ opw,
            const float* __restrict__ w1)
{
    int bi = blockIdx.x;
    int tid = threadIdx.x;
    if (bi >= WALZE_PLANES) {
        int i = (bi - WALZE_PLANES) * 256 + tid;
        const int N1 = 3*CC*CC, N2 = CC*CC, N3 = 128*2*CC;
        if (i < N1)                 g_ipw[i] = __float2bfloat16_rn(ipw[i]);
        else if (i < N1 + N2)       g_opw[i - N1] = __float2bfloat16_rn(opw[i - N1]);
        else if (i < N1 + N2 + N3)  g_w1[i - N1 - N2] = __float2bfloat16_rn(w1[i - N1 - N2]);
        return;
    }
    extern __shared__ float sx[];            // [WCH][WPAD]
    float* swo = sx + WCH * WPAD;            // [WCH][136]

    int ct = bi & 63, b = bi >> 6;
    int c0 = ct * WCH;

    for (int i = tid; i < WCH * 256; i += 256) {
        int c = i >> 8, l4 = (i & 255) * 4;
        float4 v = *(const float4*)(x + ((size_t)(b*CC + c0 + c)) * LL + l4);
        *(float4*)(sx + c * WPAD + l4) = v;
    }
    __syncthreads();

    const int c = tid & 7;
    const int lb = tid >> 3;                 // 0..31
    const float* dk = dw_w + (c0 + c) * 9;
    float d0 = dk[0], d1 = dk[1], d2 = dk[2], d3 = dk[3], d4 = dk[4],
          d5 = dk[5], d6 = dk[6], d7 = dk[7], d8 = dk[8];
    float dwb = dw_b[c0 + c];
    float gm = gamma[c0 + c] * rsqrtf(1.0f + 1e-5f);
    float bt = beta[c0 + c];
    float s0 = sh_w[0], s1 = sh_w[1], s2 = sh_w[2], s3 = sh_w[3], s4 = sh_w[4],
          s5 = sh_w[5], s6 = sh_w[6], s7 = sh_w[7], s8 = sh_w[8];
    float shb = sh_b[0];
    float mix = 1.0f / (1.0f + __expf(-mixw[0]));
    const float* row = sx + c * WPAD;

    for (int k = 0; k < 8; k++) {
#pragma unroll
        for (int j = 0; j < 4; j++) {
            int ll = lb + 32 * j;            // 0..127 within slab
            int l = k * 128 + ll;
            int h = l >> 5, w = l & 31;
            int hm = (h + 31) & 31, hp = (h + 1) & 31;
            int wm = (w + 31) & 31, wp = (w + 1) & 31;
            float v00 = row[hm*32+wm], v01 = row[hm*32+w], v02 = row[hm*32+wp];
            float v10 = row[h*32+wm],  v11 = row[h*32+w],  v12 = row[h*32+wp];
            float v20 = row[hp*32+wm], v21 = row[hp*32+w], v22 = row[hp*32+wp];
            float mo = v00*d0 + v01*d1 + v02*d2 + v10*d3 + v11*d4 + v12*d5
                     + v20*d6 + v21*d7 + v22*d8 + dwb;
            float ex = v00*s0 + v01*s1 + v02*s2 + v10*s3 + v11*s4 + v12*s5
                     + v20*s6 + v21*s7 + v22*s8 + shb;
            float xw = gelu_exact(gm * (mix*mo + (1.0f-mix)*ex + v11) + bt);
            size_t dst = ((size_t)(b*LL + l)) * (2*CC) + c0 + c;
            g_comb[dst]      = __float2bfloat16_rn(v11);
            g_comb[dst + CC] = __float2bfloat16_rn(xw);
            swo[c * 136 + ll] = xw;
        }
        __syncthreads();
#pragma unroll
        for (int j = 0; j < 4; j++) {
            int idx = tid + 256 * j;         // 0..1023
            int c2 = idx >> 7, l2 = idx & 127;
            g_xwalze[((size_t)(b*CC + c0 + c2)) * LL + k*128 + l2] =
                swo[c2 * 136 + l2];
        }
        __syncthreads();
    }
}

// ============ banded attention via mma: S = QK^T, ctx = P V =================
#define ATT_VT  0                        // 64 x 208
#define ATT_LS  (ATT_VT + 64*208)        // 13312, 64 floats
#define ATT_Q   (ATT_LS + 256)           // 13568, 64 x 144
#define ATT_K   (ATT_Q + 64*144)         // 22784, 96 x 144
#define ATT_P   ATT_Q                    // aliases Q/K (needs 64*208 <= 23040)
#define ATT_SMEM (ATT_K + 96*144)        // 36608

__global__ void __launch_bounds__(256, 4)
attn_kernel()
{
    extern __shared__ char smem[];
    const uint32_t sb = smem_u32(smem);
    int bi = blockIdx.x;
    int qt = bi & 15, h = (bi >> 4) & 7, b = bi >> 7;
    int q0 = qt * 64;
    int jlo = max(0, q0 - WHALF);
    int jhi = min(LL - 1, q0 + 63 + WHALF);
    int nrows = jhi - jlo + 1;              // 80 or 96
    int tid = threadIdx.x, lane = tid & 31, wid = tid >> 5;

    const __nv_bfloat16* qb = g_qkv + (size_t)(b*LL + q0) * (3*CC) + h*HD;
    for (int i = tid; i < 64*8; i += 256) {
        int r = i >> 3, cb = (i & 7) * 16;
        uint4 v = *(const uint4*)((const char*)(qb + (size_t)r * (3*CC)) + cb);
        *(uint4*)(smem + ATT_Q + r*144 + cb) = v;
    }
    const __nv_bfloat16* kb = g_qkv + (size_t)(b*LL + jlo) * (3*CC) + CC + h*HD;
    for (int i = tid; i < 96*8; i += 256) {
        int r = i >> 3, cb = (i & 7) * 16;
        uint4 v = make_uint4(0u, 0u, 0u, 0u);
        if (r < nrows)
            v = *(const uint4*)((const char*)(kb + (size_t)r * (3*CC)) + cb);
        *(uint4*)(smem + ATT_K + r*144 + cb) = v;
    }
    const __nv_bfloat16* vb = kb + CC;
    for (int i = tid; i < 96*16; i += 256) {
        int r = i >> 4, c4 = (i & 15) * 4;
        uint2 v = make_uint2(0u, 0u);
        if (r < nrows)
            v = *(const uint2*)(vb + (size_t)r * (3*CC) + c4);
        const __nv_bfloat16* hv = (const __nv_bfloat16*)&v;
        *(__nv_bfloat16*)(smem + ATT_VT + (c4+0)*208 + r*2) = hv[0];
        *(__nv_bfloat16*)(smem + ATT_VT + (c4+1)*208 + r*2) = hv[1];
        *(__nv_bfloat16*)(smem + ATT_VT + (c4+2)*208 + r*2) = hv[2];
        *(__nv_bfloat16*)(smem + ATT_VT + (c4+3)*208 + r*2) = hv[3];
    }
    if (tid < 64) ((float*)(smem + ATT_LS))[tid] = 0.0f;
    __syncthreads();

    const int wm0 = (wid & 1) * 32;
    const int wn0s = (wid >> 1) * 24;
    float s[2][3][4];
#pragma unroll
    for (int i = 0; i < 2; i++)
#pragma unroll
        for (int j = 0; j < 3; j++)
#pragma unroll
            for (int k = 0; k < 4; k++) s[i][j][k] = 0.0f;
    {
        const uint32_t aAddr = sb + ATT_Q + (uint32_t)((wm0 + (lane & 15)) * 144)
                             + ((uint32_t)(lane >> 4) << 4);
        const uint32_t bAddr4 = sb + ATT_K
                             + (uint32_t)((wn0s + ((lane >> 4) << 3) + (lane & 7)) * 144)
                             + (uint32_t)(((lane >> 3) & 1) << 4);
        const uint32_t bAddr2 = sb + ATT_K
                             + (uint32_t)((wn0s + 16 + (lane & 7)) * 144)
                             + (uint32_t)(((lane >> 3) & 1) << 4);
#pragma unroll
        for (int ks = 0; ks < 4; ks++) {
            const uint32_t kso = (uint32_t)(ks * 32);
            uint32_t a0[4], a1[4], bb[3][2];
            ldmx4(aAddr + kso,            a0[0], a0[1], a0[2], a0[3]);
            ldmx4(aAddr + 16*144 + kso,   a1[0], a1[1], a1[2], a1[3]);
            ldmx4(bAddr4 + kso, bb[0][0], bb[0][1], bb[1][0], bb[1][1]);
            ldmx2(bAddr2 + kso, bb[2][0], bb[2][1]);
#pragma unroll
            for (int nt = 0; nt < 3; nt++) {
                mma16(s[0][nt], a0[0], a0[1], a0[2], a0[3], bb[nt][0], bb[nt][1]);
                mma16(s[1][nt], a1[0], a1[1], a1[2], a1[3], bb[nt][0], bb[nt][1]);
            }
        }
    }
    __syncthreads();   // Q/K reads complete before P overwrites that region

    float* lsum = (float*)(smem + ATT_LS);
#pragma unroll
    for (int mt = 0; mt < 2; mt++) {
        int row = wm0 + mt * 16 + (lane >> 2);
        int qA = q0 + row, qB = qA + 8;
        float rs0 = 0.0f, rs1 = 0.0f;
#pragma unroll
        for (int nt = 0; nt < 3; nt++) {
            int col = wn0s + nt * 8 + (lane & 3) * 2;
            int gj0 = jlo + col, gj1 = gj0 + 1;
            bool a00 = (gj0 >= qA - WHALF) && (gj0 <= qA + WHALF) && (gj0 < LL);
            bool a01 = (gj1 >= qA - WHALF) && (gj1 <= qA + WHALF) && (gj1 < LL);
            bool a10 = (gj0 >= qB - WHALF) && (gj0 <= qB + WHALF) && (gj0 < LL);
            bool a11 = (gj1 >= qB - WHALF) && (gj1 <= qB + WHALF) && (gj1 < LL);
            float p00 = a00 ? __expf(s[mt][nt][0]) : 0.0f;
            float p01 = a01 ? __expf(s[mt][nt][1]) : 0.0f;
            float p10 = a10 ? __expf(s[mt][nt][2]) : 0.0f;
            float p11 = a11 ? __expf(s[mt][nt][3]) : 0.0f;
            rs0 += p00 + p01; rs1 += p10 + p11;
            *(uint32_t*)(smem + ATT_P + row*208 + col*2)     = bf2pack(p00, p01);
            *(uint32_t*)(smem + ATT_P + (row+8)*208 + col*2) = bf2pack(p10, p11);
        }
        rs0 += __shfl_xor_sync(0xffffffffu, rs0, 1);
        rs0 += __shfl_xor_sync(0xffffffffu, rs0, 2);
        rs1 += __shfl_xor_sync(0xffffffffu, rs1, 1);
        rs1 += __shfl_xor_sync(0xffffffffu, rs1, 2);
        if ((lane & 3) == 0) {
            atomicAdd(&lsum[row], rs0);
            atomicAdd(&lsum[row + 8], rs1);
        }
    }
    __syncthreads();

    const int wn0v = (wid >> 1) * 16;
    float o[2][2][4];
#pragma unroll
    for (int i = 0; i < 2; i++)
#pragma unroll
        for (int j = 0; j < 2; j++)
#pragma unroll
            for (int k = 0; k < 4; k++) o[i][j][k] = 0.0f;
    {
        const uint32_t aAddr = sb + ATT_P + (uint32_t)((wm0 + (lane & 15)) * 208)
                             + ((uint32_t)(lane >> 4) << 4);
        const uint32_t bAddr = sb + ATT_VT
                             + (uint32_t)((wn0v + ((lane >> 4) << 3) + (lane & 7)) * 208)
                             + (uint32_t)(((lane >> 3) & 1) << 4);
#pragma unroll
        for (int ks = 0; ks < 6; ks++) {
            const uint32_t kso = (uint32_t)(ks * 32);
            uint32_t a0[4], a1[4], bb[2][2];
            ldmx4(aAddr + kso,          a0[0], a0[1], a0[2], a0[3]);
            ldmx4(aAddr + 16*208 + kso, a1[0], a1[1], a1[2], a1[3]);
            ldmx4(bAddr + kso, bb[0][0], bb[0][1], bb[1][0], bb[1][1]);
#pragma unroll
            for (int nt = 0; nt < 2; nt++) {
                mma16(o[0][nt], a0[0], a0[1], a0[2], a0[3], bb[nt][0], bb[nt][1]);
                mma16(o[1][nt], a1[0], a1[1], a1[2], a1[3], bb[nt][0], bb[nt][1]);
            }
        }
    }

#pragma unroll
    for (int mt = 0; mt < 2; mt++) {
        int row = wm0 + mt * 16 + (lane >> 2);
        float inv0 = 1.0f / lsum[row];
        float inv1 = 1.0f / lsum[row + 8];
#pragma unroll
        for (int nt = 0; nt < 2; nt++) {
            int col = wn0v + nt * 8 + (lane & 3) * 2;
            __nv_bfloat16* d0 = g_ctx + (size_t)(b*LL + q0 + row) * CC + h*HD + col;
            __nv_bfloat16* d1 = d0 + (size_t)8 * CC;
            *(uint32_t*)d0 = bf2pack(o[mt][nt][0] * inv0, o[mt][nt][1] * inv0);
            *(uint32_t*)d1 = bf2pack(o[mt][nt][2] * inv1, o[mt][nt][3] * inv1);
        }
    }
}

// ---------------- host launcher ---------------------------------------------
extern "C" void kernel_launch(void* const* d_in, const int* in_sizes, int n_in,
                              void* d_out, int out_size)
{
    const float* x      = (const float*)d_in[0];
    const float* dw_w   = (const float*)d_in[1];
    const float* dw_b   = (const float*)d_in[2];
    const float* sh_w   = (const float*)d_in[3];
    const float* sh_b   = (const float*)d_in[4];
    const float* mixw   = (const float*)d_in[5];
    const float* gamma  = (const float*)d_in[6];
    const float* beta   = (const float*)d_in[7];
    const float* det_w1 = (const float*)d_in[8];
    const float* det_b1 = (const float*)d_in[9];
    const float* det_w2 = (const float*)d_in[10];
    const float* det_b2 = (const float*)d_in[11];
    const float* ipw    = (const float*)d_in[12];
    const float* ipb    = (const float*)d_in[13];
    const float* opw    = (const float*)d_in[14];
    const float* opb    = (const float*)d_in[15];
    float* out = (float*)d_out;

    __nv_bfloat16 *p_comb, *p_ctx, *p_ipw, *p_opw, *p_w1, *p_qkv;
    float *p_mask, *p_xwalze;
    cudaGetSymbolAddress((void**)&p_comb,    g_comb);
    cudaGetSymbolAddress((void**)&p_qkv,     g_qkv);
    cudaGetSymbolAddress((void**)&p_ctx,     g_ctx);
    cudaGetSymbolAddress((void**)&p_ipw,     g_ipw);
    cudaGetSymbolAddress((void**)&p_opw,     g_opw);
    cudaGetSymbolAddress((void**)&p_w1,      g_w1);
    cudaGetSymbolAddress((void**)&p_mask,    g_mask);
    cudaGetSymbolAddress((void**)&p_xwalze,  g_xwalze);

    cudaFuncSetAttribute((const void*)fused_qkv_det,
                         cudaFuncAttributeMaxDynamicSharedMemorySize, FUSED_SMEM);
    cudaFuncSetAttribute((const void*)outproj_combine,
                         cudaFuncAttributeMaxDynamicSharedMemorySize, FUSED_SMEM);
    cudaFuncSetAttribute((const void*)attn_kernel,
                         cudaFuncAttributeMaxDynamicSharedMemorySize, ATT_SMEM);
    cudaFuncSetAttribute((const void*)walze_fused,
                         cudaFuncAttributeMaxDynamicSharedMemorySize, WALZE_SMEM);

    // 1) fused walze: conv/BN/GELU + comb pack + xwalze (+ weight rounding tail)
    walze_fused<<<WALZE_PLANES + RW_BLOCKS, 256, WALZE_SMEM>>>(
        x, dw_w, dw_b, sh_w, sh_b, mixw, gamma, beta, ipw, opw, det_w1);

    // 2) fused QKV GEMM (bf16 out, Q pre-scaled) + detector GEMM/head
    fused_qkv_det<<<QKV_BLOCKS + 128, 256, FUSED_SMEM>>>(
        p_comb, p_ipw, ipb, p_qkv, p_w1, det_b1, det_w2, det_b2, p_mask);

    // 3) banded attention (mma-based, bf16 I/O, 4 CTAs/SM target)
    attn_kernel<<<BB*NHD*(LL/64), 256, ATT_SMEM>>>();

    // 4) out_proj GEMM fused with gated combine (pipelined epilogue) -> out
    {
        dim3 g(CC/128, (BB*LL)/128);
        outproj_combine<<<g, 256, FUSED_SMEM>>>(p_ctx, p_opw, opb, out,
                                                p_mask, p_xwalze);
    }
}